// round 16
// baseline (speedup 1.0000x reference)
#include <cuda_runtime.h>
#include <math.h>

#define NUM_STEPS 30

typedef unsigned long long ull;

// ---------------------------------------------------------------------------
// packed f32x2 helpers (sm_103a)
// ---------------------------------------------------------------------------
__device__ __forceinline__ ull pack2(float lo, float hi) {
    ull r; asm("mov.b64 %0, {%1, %2};" : "=l"(r) : "f"(lo), "f"(hi)); return r;
}
__device__ __forceinline__ void unpack2(ull v, float& lo, float& hi) {
    asm("mov.b64 {%0, %1}, %2;" : "=f"(lo), "=f"(hi) : "l"(v));
}
__device__ __forceinline__ ull mul2(ull a, ull b) {
    ull r; asm("mul.rn.f32x2 %0, %1, %2;" : "=l"(r) : "l"(a), "l"(b)); return r;
}
__device__ __forceinline__ ull fma2(ull a, ull b, ull c) {
    ull r; asm("fma.rn.f32x2 %0, %1, %2, %3;" : "=l"(r) : "l"(a), "l"(b), "l"(c)); return r;
}
__device__ __forceinline__ ull lerp2(ull a, ull b, ull t, ull omt) {
    return fma2(b, t, mul2(a, omt));
}

// ---------------------------------------------------------------------------
// fp32 Gauss-Jordan 4x4 inverse (well-conditioned input)
// ---------------------------------------------------------------------------
__device__ void inv4x4_f32(const float* __restrict__ A, float* __restrict__ out) {
    float m[4][8];
    #pragma unroll
    for (int i = 0; i < 4; i++) {
        #pragma unroll
        for (int j = 0; j < 4; j++) m[i][j] = A[i * 4 + j];
        #pragma unroll
        for (int j = 0; j < 4; j++) m[i][4 + j] = (i == j) ? 1.0f : 0.0f;
    }
    #pragma unroll
    for (int col = 0; col < 4; col++) {
        int piv = col;
        float best = fabsf(m[col][col]);
        #pragma unroll
        for (int r = 0; r < 4; r++) {
            if (r > col) {
                float v = fabsf(m[r][col]);
                if (v > best) { best = v; piv = r; }
            }
        }
        if (piv != col) {
            #pragma unroll
            for (int j = 0; j < 8; j++) { float t = m[col][j]; m[col][j] = m[piv][j]; m[piv][j] = t; }
        }
        float inv = 1.0f / m[col][col];
        #pragma unroll
        for (int j = 0; j < 8; j++) m[col][j] *= inv;
        #pragma unroll
        for (int r = 0; r < 4; r++) {
            if (r != col) {
                float f = m[r][col];
                #pragma unroll
                for (int j = 0; j < 8; j++) m[r][j] = fmaf(-f, m[col][j], m[r][j]);
            }
        }
    }
    #pragma unroll
    for (int i = 0; i < 4; i++)
        #pragma unroll
        for (int j = 0; j < 4; j++)
            out[i * 4 + j] = m[i][4 + j];
}

// ---------------------------------------------------------------------------
// paired-load kernel: even-aligned float2 corner loads (requires W, H*W even)
// ---------------------------------------------------------------------------
__global__ __launch_bounds__(128, 7)
void deform_paired_kernel(const float* __restrict__ verts,
                          const float* __restrict__ affine,
                          const float* __restrict__ flow,
                          float* __restrict__ out,
                          int B, int N, int D, int H, int W)
{
    __shared__ float s_inv[2][16];   // a block spans at most 2 batch values

    int gid = blockIdx.x * blockDim.x + threadIdx.x;
    long long total = (long long)B * N;

    long long g0 = (long long)blockIdx.x * blockDim.x;
    long long g1 = min(g0 + blockDim.x - 1, total - 1);
    int bmin = (int)(g0 / N);
    int bmax = (int)(g1 / N);

    if (threadIdx.x == 0) {
        inv4x4_f32(affine + bmin * 16, s_inv[0]);
        if (bmax != bmin) inv4x4_f32(affine + bmax * 16, s_inv[1]);
    }
    __syncthreads();

    if (gid >= total) return;
    int b = gid / N;
    int n = gid - b * N;

    // ---- affine transform ----
    const float* A = affine + b * 16;
    size_t vbase = ((size_t)b * N + n) * 3;
    float vx = verts[vbase + 0];
    float vy = verts[vbase + 1];
    float vz = verts[vbase + 2];

    float px = A[0] * vx + A[1] * vy + A[2]  * vz + A[3];
    float py = A[4] * vx + A[5] * vy + A[6]  * vz + A[7];
    float pz = A[8] * vx + A[9] * vy + A[10] * vz + A[11];

    const int HW  = H * W;
    const int DHW = D * HW;
    const float* base = flow + (size_t)b * 3 * (size_t)DHW;
    const float scale = 1.0f / (float)NUM_STEPS;
    const float dmax = (float)(D - 1), hmax = (float)(H - 1), wmax = (float)(W - 1);

    float xd = px, xh = py, xw = pz;

    float cfd = 1e30f, cfh = 1e30f, cfw = 1e30f;
    int cell = -1;
    ull  c01[8];
    float c2[8];

    #pragma unroll 1
    for (int s = 0; s < NUM_STEPS; s++) {
        float fd = xd - cfd;
        float fh = xh - cfh;
        float fw = xw - cfw;

        float mn = fminf(fd, fminf(fh, fw));
        float mx = fmaxf(fd, fmaxf(fh, fw));
        if (!(mn >= 0.0f && mx < 1.0f)) {
            float pdc = fminf(fmaxf(xd, 0.0f), dmax);
            float phc = fminf(fmaxf(xh, 0.0f), hmax);
            float pwc = fminf(fmaxf(xw, 0.0f), wmax);
            float fd0 = floorf(pdc), fh0 = floorf(phc), fw0 = floorf(pwc);
            int d0 = (int)fd0, h0 = (int)fh0, w0 = (int)fw0;
            fd = pdc - fd0; fh = phc - fh0; fw = pwc - fw0;
            cfd = fd0; cfh = fh0; cfw = fw0;

            int ncell = (d0 << 20) | (h0 << 10) | w0;
            if (ncell != cell) {
                cell = ncell;
                int d1 = min(d0 + 1, D - 1);
                int h1 = min(h0 + 1, H - 1);
                int w1 = min(w0 + 1, W - 1);
                int rows[4];
                rows[0] = d0 * HW + h0 * W;
                rows[1] = d0 * HW + h1 * W;
                rows[2] = d1 * HW + h0 * W;
                rows[3] = d1 * HW + h1 * W;
                int ebase = w0 & ~1;          // even-aligned, >= 0
                bool odd  = (w0 & 1) != 0;
                bool has1 = (w1 > w0);        // false only at w-border
                bool ld2  = odd && has1;      // second float2 needed (stays in-row)
                const float* p0 = base;
                const float* p1 = base + DHW;
                const float* p2 = base + 2 * DHW;
                #pragma unroll
                for (int k = 0; k < 4; k++) {
                    int e = rows[k] + ebase;  // even (W, HW even) -> 8B aligned
                    float2 a0 = __ldg((const float2*)(p0 + e));
                    float2 a1 = __ldg((const float2*)(p1 + e));
                    float2 a2 = __ldg((const float2*)(p2 + e));
                    float2 b0 = a0, b1 = a1, b2 = a2;
                    if (ld2) {
                        b0 = __ldg((const float2*)(p0 + e + 2));
                        b1 = __ldg((const float2*)(p1 + e + 2));
                        b2 = __ldg((const float2*)(p2 + e + 2));
                    }
                    // even lane: fa = (w0, w0+1); odd lane: fa = (w0-1, w0), fb = (w0+1, w0+2)
                    float c0e = odd ? a0.y : a0.x;
                    float c1e = odd ? a1.y : a1.x;
                    float c2e = odd ? a2.y : a2.x;
                    float c0o = odd ? b0.x : a0.y;
                    float c1o = odd ? b1.x : a1.y;
                    float c2o = odd ? b2.x : a2.y;
                    float c0x = has1 ? c0o : c0e;
                    float c1x = has1 ? c1o : c1e;
                    float c2x = has1 ? c2o : c2e;
                    c01[2 * k + 0] = pack2(c0e, c1e);
                    c01[2 * k + 1] = pack2(c0x, c1x);
                    c2[2 * k + 0]  = c2e;
                    c2[2 * k + 1]  = c2x;
                }
            }
        }

        float omfw = 1.0f - fw, omfh = 1.0f - fh, omfd = 1.0f - fd;
        ull W2  = pack2(fw, fw),   OW2 = pack2(omfw, omfw);
        ull H2  = pack2(fh, fh),   OH2 = pack2(omfh, omfh);
        ull D2  = pack2(fd, fd),   OD2 = pack2(omfd, omfd);

        ull l00 = lerp2(c01[0], c01[1], W2, OW2);
        ull l01 = lerp2(c01[2], c01[3], W2, OW2);
        ull l10 = lerp2(c01[4], c01[5], W2, OW2);
        ull l11 = lerp2(c01[6], c01[7], W2, OW2);
        ull m0  = lerp2(l00, l01, H2, OH2);
        ull m1  = lerp2(l10, l11, H2, OH2);
        ull r01 = lerp2(m0, m1, D2, OD2);
        float s0, s1;
        unpack2(r01, s0, s1);

        float q00 = c2[0] * omfw + c2[1] * fw;
        float q01 = c2[2] * omfw + c2[3] * fw;
        float q10 = c2[4] * omfw + c2[5] * fw;
        float q11 = c2[6] * omfw + c2[7] * fw;
        float q0  = q00 * omfh + q01 * fh;
        float q1  = q10 * omfh + q11 * fh;
        float s2  = q0 * omfd + q1 * fd;

        xd = fmaf(s0, scale, xd);
        xh = fmaf(s1, scale, xh);
        xw = fmaf(s2, scale, xw);
    }

    // ---- outputs ----
    float fix = xd - px, fiy = xh - py, fiz = xw - pz;

    const float* Inv = s_inv[b - bmin];
    float ox = Inv[0] * xd + Inv[1] * xh + Inv[2]  * xw + Inv[3];
    float oy = Inv[4] * xd + Inv[5] * xh + Inv[6]  * xw + Inv[7];
    float oz = Inv[8] * xd + Inv[9] * xh + Inv[10] * xw + Inv[11];

    size_t pb = ((size_t)b * N + n) * 3;
    out[pb + 0] = ox;
    out[pb + 1] = oy;
    out[pb + 2] = oz;

    size_t fb = (size_t)B * N * 3 + ((size_t)b * 3) * (size_t)N + n;
    out[fb + 0 * (size_t)N] = fix;
    out[fb + 1 * (size_t)N] = fiy;
    out[fb + 2 * (size_t)N] = fiz;
}

// ---------------------------------------------------------------------------
// fallback: r9 scalar-load kernel (odd W / odd HW shapes)
// ---------------------------------------------------------------------------
__global__ __launch_bounds__(128, 8)
void deform_plain_kernel(const float* __restrict__ verts,
                         const float* __restrict__ affine,
                         const float* __restrict__ flow,
                         float* __restrict__ out,
                         int B, int N, int D, int H, int W)
{
    __shared__ float s_inv[2][16];
    int gid = blockIdx.x * blockDim.x + threadIdx.x;
    long long total = (long long)B * N;
    long long g0 = (long long)blockIdx.x * blockDim.x;
    long long g1 = min(g0 + blockDim.x - 1, total - 1);
    int bmin = (int)(g0 / N);
    int bmax = (int)(g1 / N);
    if (threadIdx.x == 0) {
        inv4x4_f32(affine + bmin * 16, s_inv[0]);
        if (bmax != bmin) inv4x4_f32(affine + bmax * 16, s_inv[1]);
    }
    __syncthreads();
    if (gid >= total) return;
    int b = gid / N, n = gid - b * N;

    const float* A = affine + b * 16;
    size_t vbase = ((size_t)b * N + n) * 3;
    float vx = verts[vbase + 0], vy = verts[vbase + 1], vz = verts[vbase + 2];
    float px = A[0]*vx + A[1]*vy + A[2] *vz + A[3];
    float py = A[4]*vx + A[5]*vy + A[6] *vz + A[7];
    float pz = A[8]*vx + A[9]*vy + A[10]*vz + A[11];

    const int HW = H * W, DHW = D * HW;
    const float* base = flow + (size_t)b * 3 * (size_t)DHW;
    const float scale = 1.0f / (float)NUM_STEPS;
    const float dmax = (float)(D - 1), hmax = (float)(H - 1), wmax = (float)(W - 1);

    float xd = px, xh = py, xw = pz;
    float cfd = 1e30f, cfh = 1e30f, cfw = 1e30f;
    int cell = -1;
    ull c01[8]; float c2[8];

    #pragma unroll 1
    for (int s = 0; s < NUM_STEPS; s++) {
        float fd = xd - cfd, fh = xh - cfh, fw = xw - cfw;
        float mn = fminf(fd, fminf(fh, fw));
        float mx = fmaxf(fd, fmaxf(fh, fw));
        if (!(mn >= 0.0f && mx < 1.0f)) {
            float pdc = fminf(fmaxf(xd, 0.0f), dmax);
            float phc = fminf(fmaxf(xh, 0.0f), hmax);
            float pwc = fminf(fmaxf(xw, 0.0f), wmax);
            float fd0 = floorf(pdc), fh0 = floorf(phc), fw0 = floorf(pwc);
            int d0 = (int)fd0, h0 = (int)fh0, w0 = (int)fw0;
            fd = pdc - fd0; fh = phc - fh0; fw = pwc - fw0;
            cfd = fd0; cfh = fh0; cfw = fw0;
            int ncell = (d0 << 20) | (h0 << 10) | w0;
            if (ncell != cell) {
                cell = ncell;
                int d1 = min(d0 + 1, D - 1);
                int h1 = min(h0 + 1, H - 1);
                int w1 = min(w0 + 1, W - 1);
                int o[8];
                o[0] = d0*HW + h0*W + w0; o[1] = d0*HW + h0*W + w1;
                o[2] = d0*HW + h1*W + w0; o[3] = d0*HW + h1*W + w1;
                o[4] = d1*HW + h0*W + w0; o[5] = d1*HW + h0*W + w1;
                o[6] = d1*HW + h1*W + w0; o[7] = d1*HW + h1*W + w1;
                const float* p0 = base;
                const float* p1 = base + DHW;
                const float* p2 = base + 2 * DHW;
                #pragma unroll
                for (int k = 0; k < 8; k++) {
                    float a0 = __ldg(p0 + o[k]);
                    float a1 = __ldg(p1 + o[k]);
                    c2[k]  = __ldg(p2 + o[k]);
                    c01[k] = pack2(a0, a1);
                }
            }
        }
        float omfw = 1.0f - fw, omfh = 1.0f - fh, omfd = 1.0f - fd;
        ull W2 = pack2(fw, fw), OW2 = pack2(omfw, omfw);
        ull H2 = pack2(fh, fh), OH2 = pack2(omfh, omfh);
        ull D2 = pack2(fd, fd), OD2 = pack2(omfd, omfd);
        ull l00 = lerp2(c01[0], c01[1], W2, OW2);
        ull l01 = lerp2(c01[2], c01[3], W2, OW2);
        ull l10 = lerp2(c01[4], c01[5], W2, OW2);
        ull l11 = lerp2(c01[6], c01[7], W2, OW2);
        ull m0 = lerp2(l00, l01, H2, OH2);
        ull m1 = lerp2(l10, l11, H2, OH2);
        ull r01 = lerp2(m0, m1, D2, OD2);
        float s0, s1; unpack2(r01, s0, s1);
        float q00 = c2[0]*omfw + c2[1]*fw;
        float q01 = c2[2]*omfw + c2[3]*fw;
        float q10 = c2[4]*omfw + c2[5]*fw;
        float q11 = c2[6]*omfw + c2[7]*fw;
        float q0 = q00*omfh + q01*fh;
        float q1 = q10*omfh + q11*fh;
        float s2 = q0*omfd + q1*fd;
        xd = fmaf(s0, scale, xd);
        xh = fmaf(s1, scale, xh);
        xw = fmaf(s2, scale, xw);
    }

    float fix = xd - px, fiy = xh - py, fiz = xw - pz;
    const float* Inv = s_inv[b - bmin];
    float ox = Inv[0]*xd + Inv[1]*xh + Inv[2] *xw + Inv[3];
    float oy = Inv[4]*xd + Inv[5]*xh + Inv[6] *xw + Inv[7];
    float oz = Inv[8]*xd + Inv[9]*xh + Inv[10]*xw + Inv[11];
    size_t pb = ((size_t)b * N + n) * 3;
    out[pb + 0] = ox; out[pb + 1] = oy; out[pb + 2] = oz;
    size_t fb = (size_t)B * N * 3 + ((size_t)b * 3) * (size_t)N + n;
    out[fb + 0 * (size_t)N] = fix;
    out[fb + 1 * (size_t)N] = fiy;
    out[fb + 2 * (size_t)N] = fiz;
}

extern "C" void kernel_launch(void* const* d_in, const int* in_sizes, int n_in,
                              void* d_out, int out_size) {
    const float* verts  = (const float*)d_in[0];
    const float* affine = (const float*)d_in[1];
    const float* flow   = (const float*)d_in[2];
    float* out = (float*)d_out;

    int B = in_sizes[1] / 16;
    int N = in_sizes[0] / (3 * B);
    long long dhw = (long long)in_sizes[2] / (3LL * B);
    int D = (int)llrint(cbrt((double)dhw));
    int H = D, W = D;

    long long total = (long long)B * N;
    int threads = 128;
    int blocks = (int)((total + threads - 1) / threads);

    // paired kernel needs 8B-aligned even-base float2 rows: W and H*W even
    int HW = H * W;
    int DHW = D * HW;
    if ((W % 2 == 0) && (HW % 2 == 0) && (DHW % 2 == 0)) {
        deform_paired_kernel<<<blocks, threads>>>(verts, affine, flow, out,
                                                  B, N, D, H, W);
    } else {
        deform_plain_kernel<<<blocks, threads>>>(verts, affine, flow, out,
                                                 B, N, D, H, W);
    }
}

// round 17
// speedup vs baseline: 1.1872x; 1.1872x over previous
#include <cuda_runtime.h>
#include <math.h>

#define NUM_STEPS 30

typedef unsigned long long ull;

// ---------------------------------------------------------------------------
// packed f32x2 helpers (sm_103a)
// ---------------------------------------------------------------------------
__device__ __forceinline__ ull pack2(float lo, float hi) {
    ull r; asm("mov.b64 %0, {%1, %2};" : "=l"(r) : "f"(lo), "f"(hi)); return r;
}
__device__ __forceinline__ void unpack2(ull v, float& lo, float& hi) {
    asm("mov.b64 {%0, %1}, %2;" : "=f"(lo), "=f"(hi) : "l"(v));
}
__device__ __forceinline__ ull mul2(ull a, ull b) {
    ull r; asm("mul.rn.f32x2 %0, %1, %2;" : "=l"(r) : "l"(a), "l"(b)); return r;
}
__device__ __forceinline__ ull fma2(ull a, ull b, ull c) {
    ull r; asm("fma.rn.f32x2 %0, %1, %2, %3;" : "=l"(r) : "l"(a), "l"(b), "l"(c)); return r;
}
__device__ __forceinline__ ull lerp2(ull a, ull b, ull t, ull omt) {
    return fma2(b, t, mul2(a, omt));
}

// ---------------------------------------------------------------------------
// fp32 Gauss-Jordan 4x4 inverse (well-conditioned input)
// ---------------------------------------------------------------------------
__device__ void inv4x4_f32(const float* __restrict__ A, float* __restrict__ out) {
    float m[4][8];
    #pragma unroll
    for (int i = 0; i < 4; i++) {
        #pragma unroll
        for (int j = 0; j < 4; j++) m[i][j] = A[i * 4 + j];
        #pragma unroll
        for (int j = 0; j < 4; j++) m[i][4 + j] = (i == j) ? 1.0f : 0.0f;
    }
    #pragma unroll
    for (int col = 0; col < 4; col++) {
        int piv = col;
        float best = fabsf(m[col][col]);
        #pragma unroll
        for (int r = 0; r < 4; r++) {
            if (r > col) {
                float v = fabsf(m[r][col]);
                if (v > best) { best = v; piv = r; }
            }
        }
        if (piv != col) {
            #pragma unroll
            for (int j = 0; j < 8; j++) { float t = m[col][j]; m[col][j] = m[piv][j]; m[piv][j] = t; }
        }
        float inv = 1.0f / m[col][col];
        #pragma unroll
        for (int j = 0; j < 8; j++) m[col][j] *= inv;
        #pragma unroll
        for (int r = 0; r < 4; r++) {
            if (r != col) {
                float f = m[r][col];
                #pragma unroll
                for (int j = 0; j < 8; j++) m[r][j] = fmaf(-f, m[col][j], m[r][j]);
            }
        }
    }
    #pragma unroll
    for (int i = 0; i < 4; i++)
        #pragma unroll
        for (int j = 0; j < 4; j++)
            out[i * 4 + j] = m[i][4 + j];
}

// ---------------------------------------------------------------------------
// single fused kernel — r9 body + bit-OR in-cell test + float-origin cell id
// ---------------------------------------------------------------------------
__global__ __launch_bounds__(128, 8)
void deform_kernel(const float* __restrict__ verts,
                   const float* __restrict__ affine,
                   const float* __restrict__ flow,
                   float* __restrict__ out,
                   int B, int N, int D, int H, int W)
{
    __shared__ float s_inv[2][16];   // a block spans at most 2 batch values

    int gid = blockIdx.x * blockDim.x + threadIdx.x;
    long long total = (long long)B * N;

    long long g0 = (long long)blockIdx.x * blockDim.x;
    long long g1 = min(g0 + blockDim.x - 1, total - 1);
    int bmin = (int)(g0 / N);
    int bmax = (int)(g1 / N);

    if (threadIdx.x == 0) {
        inv4x4_f32(affine + bmin * 16, s_inv[0]);
        if (bmax != bmin) inv4x4_f32(affine + bmax * 16, s_inv[1]);
    }
    __syncthreads();

    if (gid >= total) return;
    int b = gid / N;
    int n = gid - b * N;

    // ---- affine transform ----
    const float* A = affine + b * 16;
    size_t vbase = ((size_t)b * N + n) * 3;
    float vx = verts[vbase + 0];
    float vy = verts[vbase + 1];
    float vz = verts[vbase + 2];

    float px = A[0] * vx + A[1] * vy + A[2]  * vz + A[3];
    float py = A[4] * vx + A[5] * vy + A[6]  * vz + A[7];
    float pz = A[8] * vx + A[9] * vy + A[10] * vz + A[11];

    const int HW  = H * W;
    const int DHW = D * HW;
    const float* base = flow + (size_t)b * 3 * (size_t)DHW;
    const float scale = 1.0f / (float)NUM_STEPS;
    const float dmax = (float)(D - 1), hmax = (float)(H - 1), wmax = (float)(W - 1);

    float xd = px, xh = py, xw = pz;

    // cached cell identified purely by its float origin (sentinel = never match)
    float cfd = 1e30f, cfh = 1e30f, cfw = 1e30f;
    ull  c01[8];
    float c2[8];

    #pragma unroll 1
    for (int s = 0; s < NUM_STEPS; s++) {
        float fd = xd - cfd;
        float fh = xh - cfh;
        float fw = xw - cfw;

        // in-cell iff all three fracs in [0,1): OR of bit patterns < bits(1.0f)
        // (negative -> sign bit set -> huge unsigned; >=1 -> >= 0x3F800000;
        //  1e30 sentinel and NaN also route to the slow path)
        unsigned ub = __float_as_uint(fd) | __float_as_uint(fh) | __float_as_uint(fw);
        if (ub >= 0x3F800000u) {
            float pdc = fminf(fmaxf(xd, 0.0f), dmax);
            float phc = fminf(fmaxf(xh, 0.0f), hmax);
            float pwc = fminf(fmaxf(xw, 0.0f), wmax);
            float fd0 = floorf(pdc), fh0 = floorf(phc), fw0 = floorf(pwc);
            fd = pdc - fd0; fh = phc - fh0; fw = pwc - fw0;

            if (fd0 != cfd || fh0 != cfh || fw0 != cfw) {
                cfd = fd0; cfh = fh0; cfw = fw0;
                int d0 = (int)fd0, h0 = (int)fh0, w0 = (int)fw0;
                int d1 = min(d0 + 1, D - 1);
                int h1 = min(h0 + 1, H - 1);
                int w1 = min(w0 + 1, W - 1);
                int rd0 = d0 * HW, rd1 = d1 * HW;
                int rh0 = h0 * W,  rh1 = h1 * W;
                int o[8];
                o[0] = rd0 + rh0 + w0; o[1] = rd0 + rh0 + w1;
                o[2] = rd0 + rh1 + w0; o[3] = rd0 + rh1 + w1;
                o[4] = rd1 + rh0 + w0; o[5] = rd1 + rh0 + w1;
                o[6] = rd1 + rh1 + w0; o[7] = rd1 + rh1 + w1;
                const float* p0 = base;
                const float* p1 = base + DHW;
                const float* p2 = base + 2 * DHW;
                #pragma unroll
                for (int k = 0; k < 8; k++) {
                    float a0 = __ldg(p0 + o[k]);
                    float a1 = __ldg(p1 + o[k]);
                    c2[k]  = __ldg(p2 + o[k]);
                    c01[k] = pack2(a0, a1);
                }
            }
        }

        float omfw = 1.0f - fw, omfh = 1.0f - fh, omfd = 1.0f - fd;
        ull W2  = pack2(fw, fw),   OW2 = pack2(omfw, omfw);
        ull H2  = pack2(fh, fh),   OH2 = pack2(omfh, omfh);
        ull D2  = pack2(fd, fd),   OD2 = pack2(omfd, omfd);

        ull l00 = lerp2(c01[0], c01[1], W2, OW2);
        ull l01 = lerp2(c01[2], c01[3], W2, OW2);
        ull l10 = lerp2(c01[4], c01[5], W2, OW2);
        ull l11 = lerp2(c01[6], c01[7], W2, OW2);
        ull m0  = lerp2(l00, l01, H2, OH2);
        ull m1  = lerp2(l10, l11, H2, OH2);
        ull r01 = lerp2(m0, m1, D2, OD2);
        float s0, s1;
        unpack2(r01, s0, s1);

        float q00 = c2[0] * omfw + c2[1] * fw;
        float q01 = c2[2] * omfw + c2[3] * fw;
        float q10 = c2[4] * omfw + c2[5] * fw;
        float q11 = c2[6] * omfw + c2[7] * fw;
        float q0  = q00 * omfh + q01 * fh;
        float q1  = q10 * omfh + q11 * fh;
        float s2  = q0 * omfd + q1 * fd;

        xd = fmaf(s0, scale, xd);
        xh = fmaf(s1, scale, xh);
        xw = fmaf(s2, scale, xw);
    }

    // ---- outputs ----
    float fix = xd - px, fiy = xh - py, fiz = xw - pz;

    const float* Inv = s_inv[b - bmin];
    float ox = Inv[0] * xd + Inv[1] * xh + Inv[2]  * xw + Inv[3];
    float oy = Inv[4] * xd + Inv[5] * xh + Inv[6]  * xw + Inv[7];
    float oz = Inv[8] * xd + Inv[9] * xh + Inv[10] * xw + Inv[11];

    size_t pb = ((size_t)b * N + n) * 3;
    out[pb + 0] = ox;
    out[pb + 1] = oy;
    out[pb + 2] = oz;

    size_t fb = (size_t)B * N * 3 + ((size_t)b * 3) * (size_t)N + n;
    out[fb + 0 * (size_t)N] = fix;
    out[fb + 1 * (size_t)N] = fiy;
    out[fb + 2 * (size_t)N] = fiz;
}

extern "C" void kernel_launch(void* const* d_in, const int* in_sizes, int n_in,
                              void* d_out, int out_size) {
    const float* verts  = (const float*)d_in[0];
    const float* affine = (const float*)d_in[1];
    const float* flow   = (const float*)d_in[2];
    float* out = (float*)d_out;

    int B = in_sizes[1] / 16;
    int N = in_sizes[0] / (3 * B);
    long long dhw = (long long)in_sizes[2] / (3LL * B);
    int D = (int)llrint(cbrt((double)dhw));
    int H = D, W = D;

    long long total = (long long)B * N;
    int threads = 128;
    int blocks = (int)((total + threads - 1) / threads);
    deform_kernel<<<blocks, threads>>>(verts, affine, flow, out, B, N, D, H, W);
}